// round 7
// baseline (speedup 1.0000x reference)
#include <cuda_runtime.h>
#include <cuda_bf16.h>
#include <math.h>
#include <cstdint>

// ---------------- problem constants ----------------
#define NB      4
#define LQ      4096
#define DM      256
#define NH      8
#define NL      4
#define NP      4
#define DH      32
#define S_TOT   7680
#define HLP     128
#define MQ      (NB*LQ)     // 16384
#define MV      (NB*S_TOT)  // 30720

// ---------------- scratch (static device memory) ----------------
__device__ float g_value[MV * DM];     // value = flat @ W_v (fp32)
__device__ float g_oa  [MQ * 256];     // cols 0:128 = off, 128:256 = aw logits
__device__ float g_mid [MQ * DM];      // sampled output, tf32-rounded at store
__device__ float g_BtV [256 * 256];    // W_v^T   [N,K] K-major, tf32-rounded
__device__ float g_BtOA[256 * 256];    // [W_off^T ; W_aw^T],   tf32-rounded
__device__ float g_BtO [256 * 256];    // W_out^T,              tf32-rounded
__device__ float g_bOA [256];          // [b_off ; b_aw]

// ---------------- helpers ----------------
__device__ __forceinline__ uint32_t f2tf32(float f) {
    uint32_t r;
    asm("cvt.rna.tf32.f32 %0, %1;" : "=r"(r) : "f"(f));
    return r;
}
__device__ __forceinline__ uint32_t u2tf32(uint32_t u) {
    return f2tf32(__uint_as_float(u));
}

__device__ __forceinline__ void mma_tf32(float* c, const uint32_t* a,
                                         uint32_t b0, uint32_t b1) {
    asm volatile(
        "mma.sync.aligned.m16n8k8.row.col.f32.tf32.tf32.f32 "
        "{%0,%1,%2,%3}, {%4,%5,%6,%7}, {%8,%9}, {%0,%1,%2,%3};"
        : "+f"(c[0]), "+f"(c[1]), "+f"(c[2]), "+f"(c[3])
        : "r"(a[0]), "r"(a[1]), "r"(a[2]), "r"(a[3]), "r"(b0), "r"(b1));
}

__device__ __forceinline__ void cp16(uint32_t dst, const void* src) {
    asm volatile("cp.async.ca.shared.global [%0], [%1], 16;" :: "r"(dst), "l"(src));
}
#define CP_COMMIT() asm volatile("cp.async.commit_group;" ::: "memory")
#define CP_WAIT0()  asm volatile("cp.async.wait_group 0;"  ::: "memory")

// ---------------- tf32 mma.sync GEMM v3 --------------------------------------
// 128x128 tile, 256 threads (8 warps, warp tile 32x64), BK=32, double-buffered
// cp.async for BOTH operands. Fragment loads are LDS.64 via a k-permutation
// bijection: physical smem col (2*t4) feeds instruction k-lane t4, col (2*t4+1)
// feeds k-lane t4+4 -- A and B agree, so the k-sum is unchanged.
// CVTA: apply cvt.rna.tf32 at fragment-load time (A is raw fp32 in smem).
// Two independent GEMMs fused by blockIdx.y (both N=256, K=256).
#define RS 36
#define BUFW (128 * RS)
template<bool CVTA>
__global__ __launch_bounds__(256)
void mma_gemm_kernel(const float* __restrict__ A0, const float* __restrict__ B0,
                     const float* __restrict__ bias0, float* __restrict__ C0,
                     int rows0,
                     const float* __restrict__ A1, const float* __restrict__ B1,
                     const float* __restrict__ bias1, float* __restrict__ C1)
{
    extern __shared__ uint32_t smu[];  // 4*BUFW words = 73728 B

    const float* A;  const float* Bt;  const float* bias;  float* C;
    int block_row;
    if ((int)blockIdx.y < rows0) {
        A = A0; Bt = B0; bias = bias0; C = C0; block_row = blockIdx.y * 128;
    } else {
        A = A1; Bt = B1; bias = bias1; C = C1; block_row = (blockIdx.y - rows0) * 128;
    }

    const int tid  = threadIdx.x;
    const int wid  = tid >> 5;
    const int lane = tid & 31;
    const int g8   = lane >> 2;
    const int t4   = lane & 3;
    const int block_col = blockIdx.x * 128;
    const int warp_m = (wid >> 1) * 32;
    const int warp_n = (wid & 1) * 64;

    const float* Ag = A  + (long)block_row * 256;
    const float* Bg = Bt + (long)block_col * 256;

    float acc[2][8][4];
    #pragma unroll
    for (int im = 0; im < 2; im++)
        #pragma unroll
        for (int in_ = 0; in_ < 8; in_++)
            #pragma unroll
            for (int q = 0; q < 4; q++)
                acc[im][in_][q] = 0.0f;

    // copy mapping: 1024 float4 per matrix per k-iter; 4 per thread each
    const int cr[4] = { (tid + 0)   >> 3, (tid + 256) >> 3,
                        (tid + 512) >> 3, (tid + 768) >> 3 };
    const int cc = (tid & 7) * 4;

    uint32_t sbase;
    asm("{ .reg .u64 t; cvta.to.shared.u64 t, %1; cvt.u32.u64 %0, t; }"
        : "=r"(sbase) : "l"(smu));
    uint32_t soff[4];
    #pragma unroll
    for (int j = 0; j < 4; j++) soff[j] = (uint32_t)(cr[j] * RS + cc) * 4u;

    // ---- prologue: stage k-chunk 0 into buffer 0 ----
    #pragma unroll
    for (int j = 0; j < 4; j++) {
        cp16(sbase + soff[j],            Ag + (long)cr[j] * 256 + cc);
        cp16(sbase + BUFW * 4 + soff[j], Bg + (long)cr[j] * 256 + cc);
    }
    CP_COMMIT();
    CP_WAIT0();
    __syncthreads();

    for (int it = 0; it < 8; ++it) {
        const uint32_t* As_ = smu + (it & 1) * (2 * BUFW);
        const uint32_t* Bs_ = As_ + BUFW;
        const uint32_t nb   = sbase + ((it + 1) & 1) * (2 * BUFW) * 4;

        if (it < 7) {
            const int k0 = (it + 1) * 32;
            #pragma unroll
            for (int j = 0; j < 4; j++) {
                cp16(nb + soff[j],            Ag + (long)cr[j] * 256 + k0 + cc);
                cp16(nb + BUFW * 4 + soff[j], Bg + (long)cr[j] * 256 + k0 + cc);
            }
            CP_COMMIT();
        }

        #pragma unroll
        for (int ks = 0; ks < 4; ks++) {
            const int kk2 = ks * 8 + 2 * t4;      // physical pair base
            uint32_t af[2][4];
            #pragma unroll
            for (int im = 0; im < 2; im++) {
                const int m0 = warp_m + im * 16 + g8;
                uint2 lo = *(const uint2*)&As_[ m0      * RS + kk2];
                uint2 hi = *(const uint2*)&As_[(m0 + 8) * RS + kk2];
                if (CVTA) {
                    af[im][0] = u2tf32(lo.x); af[im][2] = u2tf32(lo.y);
                    af[im][1] = u2tf32(hi.x); af[im][3] = u2tf32(hi.y);
                } else {
                    af[im][0] = lo.x; af[im][2] = lo.y;
                    af[im][1] = hi.x; af[im][3] = hi.y;
                }
            }
            #pragma unroll
            for (int in_ = 0; in_ < 8; in_++) {
                const int n0 = warp_n + in_ * 8 + g8;
                uint2 bv = *(const uint2*)&Bs_[n0 * RS + kk2];
                mma_tf32(acc[0][in_], af[0], bv.x, bv.y);
                mma_tf32(acc[1][in_], af[1], bv.x, bv.y);
            }
        }

        if (it < 7) {
            CP_WAIT0();
            __syncthreads();
        }
    }

    #pragma unroll
    for (int im = 0; im < 2; im++) {
        const int r0 = block_row + warp_m + im * 16 + g8;
        #pragma unroll
        for (int in_ = 0; in_ < 8; in_++) {
            const int col = block_col + warp_n + in_ * 8 + 2 * t4;
            const float bx = bias[col], by = bias[col + 1];
            float2 o0 = make_float2(acc[im][in_][0] + bx, acc[im][in_][1] + by);
            float2 o1 = make_float2(acc[im][in_][2] + bx, acc[im][in_][3] + by);
            *(float2*)(C + (long)r0 * 256 + col)       = o0;
            *(float2*)(C + (long)(r0 + 8) * 256 + col) = o1;
        }
    }
}

// ---------------- fused prep: 4 transposes (tf32-round) + bias concat --------
__global__ void prep_kernel(const float* __restrict__ W_v,
                            const float* __restrict__ W_off,
                            const float* __restrict__ W_aw,
                            const float* __restrict__ W_out,
                            const float* __restrict__ b_off,
                            const float* __restrict__ b_aw)
{
    const int b = blockIdx.x;
    if (b == 192) {
        int t = threadIdx.y * 32 + threadIdx.x;
        if (t < 256) g_bOA[t] = (t < 128) ? b_off[t] : b_aw[t - 128];
        return;
    }
    const float* W; float* Bt; int N, rowoff, local;
    if (b < 64)       { W = W_v;   Bt = g_BtV;  N = 256; rowoff = 0;   local = b; }
    else if (b < 96)  { W = W_off; Bt = g_BtOA; N = 128; rowoff = 0;   local = b - 64; }
    else if (b < 128) { W = W_aw;  Bt = g_BtOA; N = 128; rowoff = 128; local = b - 96; }
    else              { W = W_out; Bt = g_BtO;  N = 256; rowoff = 0;   local = b - 128; }
    const int nx = N / 32;
    const int n0 = (local % nx) * 32;
    const int k0 = (local / nx) * 32;

    __shared__ float t[32][33];
    t[threadIdx.y][threadIdx.x] = W[(k0 + threadIdx.y) * N + n0 + threadIdx.x];
    __syncthreads();
    Bt[(long)(rowoff + n0 + threadIdx.y) * 256 + k0 + threadIdx.x] =
        __uint_as_float(f2tf32(t[threadIdx.x][threadIdx.y]));
}

// ---------------- sampling kernel --------------------------------------------
__global__ __launch_bounds__(256)
void msda_sample_kernel(const float* __restrict__ ref,
                        const int*   __restrict__ shapes,
                        const int*   __restrict__ start)
{
    __shared__ float4 sp[NH][16];

    const int nq   = blockIdx.x;
    const int n    = nq / LQ;
    const int m    = threadIdx.x >> 5;
    const int lane = threadIdx.x & 31;
    const int lp   = lane & 15;
    const int l    = lp >> 2;

    {
        const int   Ti = shapes[l];
        const float Tf = (float)Ti;
        const int   st = start[l];

        const float offv  = g_oa[(long)nq * 256 +       m * 16 + lp];
        const float logit = g_oa[(long)nq * 256 + 128 + m * 16 + lp];
        const float r     = ref[(long)nq * NL + l];

        float x  = fminf(fmaxf(r * Tf + offv - 0.5f, 0.0f), Tf - 1.0f);
        float x0 = floorf(x);
        float w  = x - x0;
        int   i0 = (int)x0;
        int   i1 = min(i0 + 1, Ti - 1);
        int   g0 = (n * S_TOT + st + i0) * DM + m * DH;
        int   g1 = (n * S_TOT + st + i1) * DM + m * DH;

        float mx = logit;
        #pragma unroll
        for (int o = 8; o > 0; o >>= 1)
            mx = fmaxf(mx, __shfl_xor_sync(0xffffffffu, mx, o, 16));
        float e = expf(logit - mx);
        float ssum = e;
        #pragma unroll
        for (int o = 8; o > 0; o >>= 1)
            ssum += __shfl_xor_sync(0xffffffffu, ssum, o, 16);
        float aw = e / ssum;

        if (lane < 16)
            sp[m][lp] = make_float4(__int_as_float(g0), __int_as_float(g1), w, aw);
    }
    __syncwarp();

    const int g = lane >> 3;
    const int c = lane & 7;
    float4 acc = make_float4(0.f, 0.f, 0.f, 0.f);
    #pragma unroll
    for (int t = 0; t < 4; t++) {
        float4 pr = sp[m][t * 4 + g];
        int   ig0 = __float_as_int(pr.x);
        int   ig1 = __float_as_int(pr.y);
        float w   = pr.z;
        float aw  = pr.w;
        float4 v0 = *(const float4*)(g_value + ig0 + c * 4);
        float4 v1 = *(const float4*)(g_value + ig1 + c * 4);
        acc.x = fmaf(aw, fmaf(w, v1.x - v0.x, v0.x), acc.x);
        acc.y = fmaf(aw, fmaf(w, v1.y - v0.y, v0.y), acc.y);
        acc.z = fmaf(aw, fmaf(w, v1.z - v0.z, v0.z), acc.z);
        acc.w = fmaf(aw, fmaf(w, v1.w - v0.w, v0.w), acc.w);
    }
    #pragma unroll
    for (int o = 8; o <= 16; o <<= 1) {
        acc.x += __shfl_xor_sync(0xffffffffu, acc.x, o);
        acc.y += __shfl_xor_sync(0xffffffffu, acc.y, o);
        acc.z += __shfl_xor_sync(0xffffffffu, acc.z, o);
        acc.w += __shfl_xor_sync(0xffffffffu, acc.w, o);
    }
    if (lane < 8) {
        acc.x = __uint_as_float(f2tf32(acc.x));
        acc.y = __uint_as_float(f2tf32(acc.y));
        acc.z = __uint_as_float(f2tf32(acc.z));
        acc.w = __uint_as_float(f2tf32(acc.w));
        *(float4*)(g_mid + (long)nq * DM + m * DH + c * 4) = acc;
    }
}

// ---------------- launch ------------------------------------------------------
extern "C" void kernel_launch(void* const* d_in, const int* in_sizes, int n_in,
                              void* d_out, int out_size)
{
    const float* query  = (const float*)d_in[0];
    const float* refpts = (const float*)d_in[1];
    const float* flat   = (const float*)d_in[2];
    const int*   shapes = (const int*)  d_in[3];
    const int*   start  = (const int*)  d_in[4];
    const float* W_off  = (const float*)d_in[5];
    const float* b_off  = (const float*)d_in[6];
    const float* W_aw   = (const float*)d_in[7];
    const float* b_aw   = (const float*)d_in[8];
    const float* W_v    = (const float*)d_in[9];
    const float* b_v    = (const float*)d_in[10];
    const float* W_out  = (const float*)d_in[11];
    const float* b_out  = (const float*)d_in[12];
    float* out = (float*)d_out;

    float *p_value, *p_oa, *p_mid, *p_BtV, *p_BtOA, *p_BtO, *p_bOA;
    cudaGetSymbolAddress((void**)&p_value, g_value);
    cudaGetSymbolAddress((void**)&p_oa,    g_oa);
    cudaGetSymbolAddress((void**)&p_mid,   g_mid);
    cudaGetSymbolAddress((void**)&p_BtV,   g_BtV);
    cudaGetSymbolAddress((void**)&p_BtOA,  g_BtOA);
    cudaGetSymbolAddress((void**)&p_BtO,   g_BtO);
    cudaGetSymbolAddress((void**)&p_bOA,   g_bOA);

    const int smem_bytes = 4 * BUFW * 4;   // 73728
    cudaFuncSetAttribute(mma_gemm_kernel<true>,
                         cudaFuncAttributeMaxDynamicSharedMemorySize, smem_bytes);
    cudaFuncSetAttribute(mma_gemm_kernel<false>,
                         cudaFuncAttributeMaxDynamicSharedMemorySize, smem_bytes);

    // prep: weight transposes (tf32-rounded) + bias concat
    prep_kernel<<<193, dim3(32, 32)>>>(W_v, W_off, W_aw, W_out, b_off, b_aw);

    // fused GEMM1: value = flat@BtV + b_v  |  [off|aw] = query@BtOA + bOA
    mma_gemm_kernel<true><<<dim3(2, MV / 128 + MQ / 128), 256, smem_bytes>>>(
        flat, p_BtV, b_v, p_value, MV / 128,
        query, p_BtOA, p_bOA, p_oa);

    // sampling (writes tf32-rounded g_mid)
    msda_sample_kernel<<<MQ, 256>>>(refpts, shapes, start);

    // GEMM2: out = mid @ BtO + b_out (A already tf32 -> raw fragments)
    mma_gemm_kernel<false><<<dim3(2, MQ / 128), 256, smem_bytes>>>(
        p_mid, p_BtO, b_out, out, MQ / 128,
        p_mid, p_BtO, b_out, out);
}

// round 8
// speedup vs baseline: 1.0795x; 1.0795x over previous
#include <cuda_runtime.h>
#include <cuda_bf16.h>
#include <math.h>
#include <cstdint>

// ---------------- problem constants ----------------
#define NB      4
#define LQ      4096
#define DM      256
#define NH      8
#define NL      4
#define NP      4
#define DH      32
#define S_TOT   7680
#define HLP     128
#define MQ      (NB*LQ)     // 16384
#define MV      (NB*S_TOT)  // 30720

// ---------------- scratch (static device memory) ----------------
__device__ float g_value[MV * DM];     // value = flat @ W_v (fp32)
__device__ float g_oa  [MQ * 256];     // cols 0:128 = off, 128:256 = aw logits
__device__ float g_mid [MQ * DM];      // sampled output, tf32-rounded at store
__device__ float g_BtV [256 * 256];    // W_v^T   [N,K] K-major, tf32-rounded
__device__ float g_BtOA[256 * 256];    // [W_off^T ; W_aw^T],   tf32-rounded
__device__ float g_BtO [256 * 256];    // W_out^T,              tf32-rounded
__device__ float g_bOA [256];          // [b_off ; b_aw]

// ---------------- helpers ----------------
__device__ __forceinline__ uint32_t f2tf32(float f) {
    uint32_t r;
    asm("cvt.rna.tf32.f32 %0, %1;" : "=r"(r) : "f"(f));
    return r;
}
__device__ __forceinline__ uint32_t u2tf32(uint32_t u) {
    return f2tf32(__uint_as_float(u));
}

__device__ __forceinline__ void mma_tf32(float* c, const uint32_t* a,
                                         uint32_t b0, uint32_t b1) {
    asm volatile(
        "mma.sync.aligned.m16n8k8.row.col.f32.tf32.tf32.f32 "
        "{%0,%1,%2,%3}, {%4,%5,%6,%7}, {%8,%9}, {%0,%1,%2,%3};"
        : "+f"(c[0]), "+f"(c[1]), "+f"(c[2]), "+f"(c[3])
        : "r"(a[0]), "r"(a[1]), "r"(a[2]), "r"(a[3]), "r"(b0), "r"(b1));
}

__device__ __forceinline__ void cp16(uint32_t dst, const void* src) {
    asm volatile("cp.async.ca.shared.global [%0], [%1], 16;" :: "r"(dst), "l"(src));
}
#define CP_COMMIT() asm volatile("cp.async.commit_group;" ::: "memory")
#define CP_WAIT0()  asm volatile("cp.async.wait_group 0;"  ::: "memory")

// ---------------- tf32 mma.sync GEMM v4 --------------------------------------
// 128x128 tile, 256 threads (8 warps, warp tile 32x64), BK=32, double-buffered
// cp.async for BOTH operands. Fragment loads are LDS.64 via the k-permutation
// bijection (physical cols 2t4/2t4+1 <-> k-lanes t4/t4+4; A and B agree).
// RS=40: fragment addr in 8B units = 20*g8 + t4 -> all half-warp lanes hit
// distinct 8B groups => conflict-free LDS.64 (R7's RS=36 had 2-way conflicts).
// CVTA: apply cvt.rna.tf32 at fragment-load time (A raw fp32 in smem).
#define RS 40
#define BUFW (128 * RS)
template<bool CVTA>
__global__ __launch_bounds__(256)
void mma_gemm_kernel(const float* __restrict__ A0, const float* __restrict__ B0,
                     const float* __restrict__ bias0, float* __restrict__ C0,
                     int rows0,
                     const float* __restrict__ A1, const float* __restrict__ B1,
                     const float* __restrict__ bias1, float* __restrict__ C1)
{
    extern __shared__ uint32_t smu[];  // 4*BUFW words = 81920 B

    const float* A;  const float* Bt;  const float* bias;  float* C;
    int block_row;
    if ((int)blockIdx.y < rows0) {
        A = A0; Bt = B0; bias = bias0; C = C0; block_row = blockIdx.y * 128;
    } else {
        A = A1; Bt = B1; bias = bias1; C = C1; block_row = (blockIdx.y - rows0) * 128;
    }

    const int tid  = threadIdx.x;
    const int wid  = tid >> 5;
    const int lane = tid & 31;
    const int g8   = lane >> 2;
    const int t4   = lane & 3;
    const int block_col = blockIdx.x * 128;
    const int warp_m = (wid >> 1) * 32;
    const int warp_n = (wid & 1) * 64;

    const float* Ag = A  + (long)block_row * 256;
    const float* Bg = Bt + (long)block_col * 256;

    float acc[2][8][4];
    #pragma unroll
    for (int im = 0; im < 2; im++)
        #pragma unroll
        for (int in_ = 0; in_ < 8; in_++)
            #pragma unroll
            for (int q = 0; q < 4; q++)
                acc[im][in_][q] = 0.0f;

    // copy mapping: 1024 float4 per matrix per k-iter; 4 per thread each
    const int cr[4] = { (tid + 0)   >> 3, (tid + 256) >> 3,
                        (tid + 512) >> 3, (tid + 768) >> 3 };
    const int cc = (tid & 7) * 4;

    uint32_t sbase;
    asm("{ .reg .u64 t; cvta.to.shared.u64 t, %1; cvt.u32.u64 %0, t; }"
        : "=r"(sbase) : "l"(smu));
    uint32_t soff[4];
    #pragma unroll
    for (int j = 0; j < 4; j++) soff[j] = (uint32_t)(cr[j] * RS + cc) * 4u;

    // ---- prologue: stage k-chunk 0 into buffer 0 ----
    #pragma unroll
    for (int j = 0; j < 4; j++) {
        cp16(sbase + soff[j],            Ag + (long)cr[j] * 256 + cc);
        cp16(sbase + BUFW * 4 + soff[j], Bg + (long)cr[j] * 256 + cc);
    }
    CP_COMMIT();
    CP_WAIT0();
    __syncthreads();

    for (int it = 0; it < 8; ++it) {
        const uint32_t* As_ = smu + (it & 1) * (2 * BUFW);
        const uint32_t* Bs_ = As_ + BUFW;
        const uint32_t nb   = sbase + ((it + 1) & 1) * (2 * BUFW) * 4;

        if (it < 7) {
            const int k0 = (it + 1) * 32;
            #pragma unroll
            for (int j = 0; j < 4; j++) {
                cp16(nb + soff[j],            Ag + (long)cr[j] * 256 + k0 + cc);
                cp16(nb + BUFW * 4 + soff[j], Bg + (long)cr[j] * 256 + k0 + cc);
            }
            CP_COMMIT();
        }

        #pragma unroll
        for (int ks = 0; ks < 4; ks++) {
            const int kk2 = ks * 8 + 2 * t4;      // physical pair base (8B aligned)
            uint32_t af[2][4];
            #pragma unroll
            for (int im = 0; im < 2; im++) {
                const int m0 = warp_m + im * 16 + g8;
                uint2 lo = *(const uint2*)&As_[ m0      * RS + kk2];
                uint2 hi = *(const uint2*)&As_[(m0 + 8) * RS + kk2];
                if (CVTA) {
                    af[im][0] = u2tf32(lo.x); af[im][2] = u2tf32(lo.y);
                    af[im][1] = u2tf32(hi.x); af[im][3] = u2tf32(hi.y);
                } else {
                    af[im][0] = lo.x; af[im][2] = lo.y;
                    af[im][1] = hi.x; af[im][3] = hi.y;
                }
            }
            #pragma unroll
            for (int in_ = 0; in_ < 8; in_++) {
                const int n0 = warp_n + in_ * 8 + g8;
                uint2 bv = *(const uint2*)&Bs_[n0 * RS + kk2];
                mma_tf32(acc[0][in_], af[0], bv.x, bv.y);
                mma_tf32(acc[1][in_], af[1], bv.x, bv.y);
            }
        }

        if (it < 7) {
            CP_WAIT0();
            __syncthreads();
        }
    }

    #pragma unroll
    for (int im = 0; im < 2; im++) {
        const int r0 = block_row + warp_m + im * 16 + g8;
        #pragma unroll
        for (int in_ = 0; in_ < 8; in_++) {
            const int col = block_col + warp_n + in_ * 8 + 2 * t4;
            const float bx = bias[col], by = bias[col + 1];
            float2 o0 = make_float2(acc[im][in_][0] + bx, acc[im][in_][1] + by);
            float2 o1 = make_float2(acc[im][in_][2] + bx, acc[im][in_][3] + by);
            *(float2*)(C + (long)r0 * 256 + col)       = o0;
            *(float2*)(C + (long)(r0 + 8) * 256 + col) = o1;
        }
    }
}

// ---------------- fused prep: 4 transposes (tf32-round) + bias concat --------
__global__ void prep_kernel(const float* __restrict__ W_v,
                            const float* __restrict__ W_off,
                            const float* __restrict__ W_aw,
                            const float* __restrict__ W_out,
                            const float* __restrict__ b_off,
                            const float* __restrict__ b_aw)
{
    const int b = blockIdx.x;
    if (b == 192) {
        int t = threadIdx.y * 32 + threadIdx.x;
        if (t < 256) g_bOA[t] = (t < 128) ? b_off[t] : b_aw[t - 128];
        return;
    }
    const float* W; float* Bt; int N, rowoff, local;
    if (b < 64)       { W = W_v;   Bt = g_BtV;  N = 256; rowoff = 0;   local = b; }
    else if (b < 96)  { W = W_off; Bt = g_BtOA; N = 128; rowoff = 0;   local = b - 64; }
    else if (b < 128) { W = W_aw;  Bt = g_BtOA; N = 128; rowoff = 128; local = b - 96; }
    else              { W = W_out; Bt = g_BtO;  N = 256; rowoff = 0;   local = b - 128; }
    const int nx = N / 32;
    const int n0 = (local % nx) * 32;
    const int k0 = (local / nx) * 32;

    __shared__ float t[32][33];
    t[threadIdx.y][threadIdx.x] = W[(k0 + threadIdx.y) * N + n0 + threadIdx.x];
    __syncthreads();
    Bt[(long)(rowoff + n0 + threadIdx.y) * 256 + k0 + threadIdx.x] =
        __uint_as_float(f2tf32(t[threadIdx.x][threadIdx.y]));
}

// ---------------- sampling kernel --------------------------------------------
__global__ __launch_bounds__(256)
void msda_sample_kernel(const float* __restrict__ ref,
                        const int*   __restrict__ shapes,
                        const int*   __restrict__ start)
{
    __shared__ float4 sp[NH][16];

    const int nq   = blockIdx.x;
    const int n    = nq / LQ;
    const int m    = threadIdx.x >> 5;
    const int lane = threadIdx.x & 31;
    const int lp   = lane & 15;
    const int l    = lp >> 2;

    {
        const int   Ti = shapes[l];
        const float Tf = (float)Ti;
        const int   st = start[l];

        const float offv  = g_oa[(long)nq * 256 +       m * 16 + lp];
        const float logit = g_oa[(long)nq * 256 + 128 + m * 16 + lp];
        const float r     = ref[(long)nq * NL + l];

        float x  = fminf(fmaxf(r * Tf + offv - 0.5f, 0.0f), Tf - 1.0f);
        float x0 = floorf(x);
        float w  = x - x0;
        int   i0 = (int)x0;
        int   i1 = min(i0 + 1, Ti - 1);
        int   g0 = (n * S_TOT + st + i0) * DM + m * DH;
        int   g1 = (n * S_TOT + st + i1) * DM + m * DH;

        float mx = logit;
        #pragma unroll
        for (int o = 8; o > 0; o >>= 1)
            mx = fmaxf(mx, __shfl_xor_sync(0xffffffffu, mx, o, 16));
        float e = expf(logit - mx);
        float ssum = e;
        #pragma unroll
        for (int o = 8; o > 0; o >>= 1)
            ssum += __shfl_xor_sync(0xffffffffu, ssum, o, 16);
        float aw = e / ssum;

        if (lane < 16)
            sp[m][lp] = make_float4(__int_as_float(g0), __int_as_float(g1), w, aw);
    }
    __syncwarp();

    const int g = lane >> 3;
    const int c = lane & 7;
    float4 acc = make_float4(0.f, 0.f, 0.f, 0.f);
    #pragma unroll
    for (int t = 0; t < 4; t++) {
        float4 pr = sp[m][t * 4 + g];
        int   ig0 = __float_as_int(pr.x);
        int   ig1 = __float_as_int(pr.y);
        float w   = pr.z;
        float aw  = pr.w;
        float4 v0 = *(const float4*)(g_value + ig0 + c * 4);
        float4 v1 = *(const float4*)(g_value + ig1 + c * 4);
        acc.x = fmaf(aw, fmaf(w, v1.x - v0.x, v0.x), acc.x);
        acc.y = fmaf(aw, fmaf(w, v1.y - v0.y, v0.y), acc.y);
        acc.z = fmaf(aw, fmaf(w, v1.z - v0.z, v0.z), acc.z);
        acc.w = fmaf(aw, fmaf(w, v1.w - v0.w, v0.w), acc.w);
    }
    #pragma unroll
    for (int o = 8; o <= 16; o <<= 1) {
        acc.x += __shfl_xor_sync(0xffffffffu, acc.x, o);
        acc.y += __shfl_xor_sync(0xffffffffu, acc.y, o);
        acc.z += __shfl_xor_sync(0xffffffffu, acc.z, o);
        acc.w += __shfl_xor_sync(0xffffffffu, acc.w, o);
    }
    if (lane < 8) {
        acc.x = __uint_as_float(f2tf32(acc.x));
        acc.y = __uint_as_float(f2tf32(acc.y));
        acc.z = __uint_as_float(f2tf32(acc.z));
        acc.w = __uint_as_float(f2tf32(acc.w));
        *(float4*)(g_mid + (long)nq * DM + m * DH + c * 4) = acc;
    }
}

// ---------------- launch ------------------------------------------------------
extern "C" void kernel_launch(void* const* d_in, const int* in_sizes, int n_in,
                              void* d_out, int out_size)
{
    const float* query  = (const float*)d_in[0];
    const float* refpts = (const float*)d_in[1];
    const float* flat   = (const float*)d_in[2];
    const int*   shapes = (const int*)  d_in[3];
    const int*   start  = (const int*)  d_in[4];
    const float* W_off  = (const float*)d_in[5];
    const float* b_off  = (const float*)d_in[6];
    const float* W_aw   = (const float*)d_in[7];
    const float* b_aw   = (const float*)d_in[8];
    const float* W_v    = (const float*)d_in[9];
    const float* b_v    = (const float*)d_in[10];
    const float* W_out  = (const float*)d_in[11];
    const float* b_out  = (const float*)d_in[12];
    float* out = (float*)d_out;

    float *p_value, *p_oa, *p_mid, *p_BtV, *p_BtOA, *p_BtO, *p_bOA;
    cudaGetSymbolAddress((void**)&p_value, g_value);
    cudaGetSymbolAddress((void**)&p_oa,    g_oa);
    cudaGetSymbolAddress((void**)&p_mid,   g_mid);
    cudaGetSymbolAddress((void**)&p_BtV,   g_BtV);
    cudaGetSymbolAddress((void**)&p_BtOA,  g_BtOA);
    cudaGetSymbolAddress((void**)&p_BtO,   g_BtO);
    cudaGetSymbolAddress((void**)&p_bOA,   g_bOA);

    const int smem_bytes = 4 * BUFW * 4;   // 81920
    cudaFuncSetAttribute(mma_gemm_kernel<true>,
                         cudaFuncAttributeMaxDynamicSharedMemorySize, smem_bytes);
    cudaFuncSetAttribute(mma_gemm_kernel<false>,
                         cudaFuncAttributeMaxDynamicSharedMemorySize, smem_bytes);

    // prep: weight transposes (tf32-rounded) + bias concat
    prep_kernel<<<193, dim3(32, 32)>>>(W_v, W_off, W_aw, W_out, b_off, b_aw);

    // fused GEMM1: value = flat@BtV + b_v  |  [off|aw] = query@BtOA + bOA
    mma_gemm_kernel<true><<<dim3(2, MV / 128 + MQ / 128), 256, smem_bytes>>>(
        flat, p_BtV, b_v, p_value, MV / 128,
        query, p_BtOA, p_bOA, p_oa);

    // sampling (writes tf32-rounded g_mid)
    msda_sample_kernel<<<MQ, 256>>>(refpts, shapes, start);

    // GEMM2: out = mid @ BtO + b_out (A already tf32 -> raw fragments)
    mma_gemm_kernel<false><<<dim3(2, MQ / 128), 256, smem_bytes>>>(
        p_mid, p_BtO, b_out, out, MQ / 128,
        p_mid, p_BtO, b_out, out);
}

// round 9
// speedup vs baseline: 1.1910x; 1.1033x over previous
#include <cuda_runtime.h>
#include <cuda_bf16.h>
#include <math.h>
#include <cstdint>

// ---------------- problem constants ----------------
#define NB      4
#define LQ      4096
#define DM      256
#define NH      8
#define NL      4
#define NP      4
#define DH      32
#define S_TOT   7680
#define HLP     128
#define MQ      (NB*LQ)     // 16384
#define MV      (NB*S_TOT)  // 30720

// ---------------- scratch (static device memory) ----------------
__device__ float g_value[MV * DM];     // value = flat @ W_v (fp32)
__device__ float g_oa  [MQ * 256];     // cols 0:128 = off, 128:256 = aw logits
__device__ float g_mid [MQ * DM];      // sampled output, tf32-rounded at store
__device__ float g_BtV [256 * 256];    // W_v^T   [N,K] K-major, tf32-rounded
__device__ float g_BtOA[256 * 256];    // [W_off^T ; W_aw^T],   tf32-rounded
__device__ float g_BtO [256 * 256];    // W_out^T,              tf32-rounded
__device__ float g_bOA [256];          // [b_off ; b_aw]

// ---------------- helpers ----------------
__device__ __forceinline__ uint32_t f2tf32(float f) {
    uint32_t r;
    asm("cvt.rna.tf32.f32 %0, %1;" : "=r"(r) : "f"(f));
    return r;
}
__device__ __forceinline__ uint32_t u2tf32(uint32_t u) {
    return f2tf32(__uint_as_float(u));
}

__device__ __forceinline__ void mma_tf32(float* c, const uint32_t* a,
                                         uint32_t b0, uint32_t b1) {
    asm volatile(
        "mma.sync.aligned.m16n8k8.row.col.f32.tf32.tf32.f32 "
        "{%0,%1,%2,%3}, {%4,%5,%6,%7}, {%8,%9}, {%0,%1,%2,%3};"
        : "+f"(c[0]), "+f"(c[1]), "+f"(c[2]), "+f"(c[3])
        : "r"(a[0]), "r"(a[1]), "r"(a[2]), "r"(a[3]), "r"(b0), "r"(b1));
}

// ldmatrix x4: four 8-row x 16B tiles, distributed lane 4r+c <- row r word c.
__device__ __forceinline__ void ldsm_x4(uint32_t* r, uint32_t addr) {
    asm volatile("ldmatrix.sync.aligned.m8n8.x4.shared.b16 {%0,%1,%2,%3}, [%4];"
                 : "=r"(r[0]), "=r"(r[1]), "=r"(r[2]), "=r"(r[3]) : "r"(addr));
}

__device__ __forceinline__ void cp16(uint32_t dst, const void* src) {
    asm volatile("cp.async.ca.shared.global [%0], [%1], 16;" :: "r"(dst), "l"(src));
}
#define CP_COMMIT() asm volatile("cp.async.commit_group;" ::: "memory")
#define CP_WAIT0()  asm volatile("cp.async.wait_group 0;"  ::: "memory")

// ---------------- tf32 mma.sync GEMM v5 (R6 + ldmatrix fragments) ------------
// 128x128 tile, 256 threads (8 warps, warp tile 32x64), BK=32, double-buffered
// cp.async for BOTH operands; fragment loads via LDSM.x4 (A: 2/ks, B: 4/ks).
// RS=36: rows stride 4 words mod 32 -> every LDSM 8-row phase conflict-free.
// CVTA: cvt.rna.tf32 applied to LDSM outputs (A is raw fp32 in smem).
#define RS 36
#define BUFW (128 * RS)
template<bool CVTA>
__global__ __launch_bounds__(256)
void mma_gemm_kernel(const float* __restrict__ A0, const float* __restrict__ B0,
                     const float* __restrict__ bias0, float* __restrict__ C0,
                     int rows0,
                     const float* __restrict__ A1, const float* __restrict__ B1,
                     const float* __restrict__ bias1, float* __restrict__ C1)
{
    extern __shared__ uint32_t smu[];  // 4*BUFW words = 73728 B

    const float* A;  const float* Bt;  const float* bias;  float* C;
    int block_row;
    if ((int)blockIdx.y < rows0) {
        A = A0; Bt = B0; bias = bias0; C = C0; block_row = blockIdx.y * 128;
    } else {
        A = A1; Bt = B1; bias = bias1; C = C1; block_row = (blockIdx.y - rows0) * 128;
    }

    const int tid  = threadIdx.x;
    const int wid  = tid >> 5;
    const int lane = tid & 31;
    const int g8   = lane >> 2;
    const int t4   = lane & 3;
    const int block_col = blockIdx.x * 128;
    const int warp_m = (wid >> 1) * 32;
    const int warp_n = (wid & 1) * 64;

    const float* Ag = A  + (long)block_row * 256;
    const float* Bg = Bt + (long)block_col * 256;

    float acc[2][8][4];
    #pragma unroll
    for (int im = 0; im < 2; im++)
        #pragma unroll
        for (int in_ = 0; in_ < 8; in_++)
            #pragma unroll
            for (int q = 0; q < 4; q++)
                acc[im][in_][q] = 0.0f;

    // copy mapping: 1024 float4 per matrix per k-iter; 4 per thread each
    const int cr[4] = { (tid + 0)   >> 3, (tid + 256) >> 3,
                        (tid + 512) >> 3, (tid + 768) >> 3 };
    const int cc = (tid & 7) * 4;

    uint32_t sbase;
    asm("{ .reg .u64 t; cvta.to.shared.u64 t, %1; cvt.u32.u64 %0, t; }"
        : "=r"(sbase) : "l"(smu));
    uint32_t soff[4];
    #pragma unroll
    for (int j = 0; j < 4; j++) soff[j] = (uint32_t)(cr[j] * RS + cc) * 4u;

    // ---- LDSM per-lane fragment addresses (byte offsets within a buffer) ----
    // A tiles (per im): rows warp_m+im*16+(lane&15), word (lane>>4)*4 (+ks*8)
    uint32_t aoff[2];
    #pragma unroll
    for (int im = 0; im < 2; im++)
        aoff[im] = (uint32_t)((warp_m + im * 16 + (lane & 15)) * RS
                              + (lane >> 4) * 4) * 4u;
    // B tiles (per j, n-blocks 2j/2j+1): rows warp_n+j*16+(lane&7)+(lane>>4)*8,
    // word ((lane>>3)&1)*4 (+ks*8); B matrix lives at +BUFW words.
    uint32_t boff[4];
    #pragma unroll
    for (int j = 0; j < 4; j++)
        boff[j] = (uint32_t)((warp_n + j * 16 + (lane & 7) + (lane >> 4) * 8) * RS
                             + ((lane >> 3) & 1) * 4) * 4u + BUFW * 4u;

    // ---- prologue: stage k-chunk 0 into buffer 0 ----
    #pragma unroll
    for (int j = 0; j < 4; j++) {
        cp16(sbase + soff[j],            Ag + (long)cr[j] * 256 + cc);
        cp16(sbase + BUFW * 4 + soff[j], Bg + (long)cr[j] * 256 + cc);
    }
    CP_COMMIT();
    CP_WAIT0();
    __syncthreads();

    for (int it = 0; it < 8; ++it) {
        const uint32_t buf = sbase + (uint32_t)(it & 1) * (2 * BUFW) * 4u;
        const uint32_t nb  = sbase + (uint32_t)((it + 1) & 1) * (2 * BUFW) * 4u;

        if (it < 7) {
            const int k0 = (it + 1) * 32;
            #pragma unroll
            for (int j = 0; j < 4; j++) {
                cp16(nb + soff[j],            Ag + (long)cr[j] * 256 + k0 + cc);
                cp16(nb + BUFW * 4 + soff[j], Bg + (long)cr[j] * 256 + k0 + cc);
            }
            CP_COMMIT();
        }

        #pragma unroll
        for (int ks = 0; ks < 4; ks++) {
            const uint32_t kb = (uint32_t)(ks * 8) * 4u;   // +32B per ks
            uint32_t af[2][4];
            ldsm_x4(af[0], buf + aoff[0] + kb);
            ldsm_x4(af[1], buf + aoff[1] + kb);
            if (CVTA) {
                #pragma unroll
                for (int im = 0; im < 2; im++)
                    #pragma unroll
                    for (int q = 0; q < 4; q++)
                        af[im][q] = u2tf32(af[im][q]);
            }
            #pragma unroll
            for (int j = 0; j < 4; j++) {
                uint32_t bf[4];
                ldsm_x4(bf, buf + boff[j] + kb);
                mma_tf32(acc[0][2 * j    ], af[0], bf[0], bf[1]);
                mma_tf32(acc[0][2 * j + 1], af[0], bf[2], bf[3]);
                mma_tf32(acc[1][2 * j    ], af[1], bf[0], bf[1]);
                mma_tf32(acc[1][2 * j + 1], af[1], bf[2], bf[3]);
            }
        }

        if (it < 7) {
            CP_WAIT0();
            __syncthreads();
        }
    }

    #pragma unroll
    for (int im = 0; im < 2; im++) {
        const int r0 = block_row + warp_m + im * 16 + g8;
        #pragma unroll
        for (int in_ = 0; in_ < 8; in_++) {
            const int col = block_col + warp_n + in_ * 8 + 2 * t4;
            const float bx = bias[col], by = bias[col + 1];
            float2 o0 = make_float2(acc[im][in_][0] + bx, acc[im][in_][1] + by);
            float2 o1 = make_float2(acc[im][in_][2] + bx, acc[im][in_][3] + by);
            *(float2*)(C + (long)r0 * 256 + col)       = o0;
            *(float2*)(C + (long)(r0 + 8) * 256 + col) = o1;
        }
    }
}

// ---------------- fused prep: 4 transposes (tf32-round) + bias concat --------
__global__ void prep_kernel(const float* __restrict__ W_v,
                            const float* __restrict__ W_off,
                            const float* __restrict__ W_aw,
                            const float* __restrict__ W_out,
                            const float* __restrict__ b_off,
                            const float* __restrict__ b_aw)
{
    const int b = blockIdx.x;
    if (b == 192) {
        int t = threadIdx.y * 32 + threadIdx.x;
        if (t < 256) g_bOA[t] = (t < 128) ? b_off[t] : b_aw[t - 128];
        return;
    }
    const float* W; float* Bt; int N, rowoff, local;
    if (b < 64)       { W = W_v;   Bt = g_BtV;  N = 256; rowoff = 0;   local = b; }
    else if (b < 96)  { W = W_off; Bt = g_BtOA; N = 128; rowoff = 0;   local = b - 64; }
    else if (b < 128) { W = W_aw;  Bt = g_BtOA; N = 128; rowoff = 128; local = b - 96; }
    else              { W = W_out; Bt = g_BtO;  N = 256; rowoff = 0;   local = b - 128; }
    const int nx = N / 32;
    const int n0 = (local % nx) * 32;
    const int k0 = (local / nx) * 32;

    __shared__ float t[32][33];
    t[threadIdx.y][threadIdx.x] = W[(k0 + threadIdx.y) * N + n0 + threadIdx.x];
    __syncthreads();
    Bt[(long)(rowoff + n0 + threadIdx.y) * 256 + k0 + threadIdx.x] =
        __uint_as_float(f2tf32(t[threadIdx.x][threadIdx.y]));
}

// ---------------- sampling kernel --------------------------------------------
__global__ __launch_bounds__(256)
void msda_sample_kernel(const float* __restrict__ ref,
                        const int*   __restrict__ shapes,
                        const int*   __restrict__ start)
{
    __shared__ float4 sp[NH][16];

    const int nq   = blockIdx.x;
    const int n    = nq / LQ;
    const int m    = threadIdx.x >> 5;
    const int lane = threadIdx.x & 31;
    const int lp   = lane & 15;
    const int l    = lp >> 2;

    {
        const int   Ti = shapes[l];
        const float Tf = (float)Ti;
        const int   st = start[l];

        const float offv  = g_oa[(long)nq * 256 +       m * 16 + lp];
        const float logit = g_oa[(long)nq * 256 + 128 + m * 16 + lp];
        const float r     = ref[(long)nq * NL + l];

        float x  = fminf(fmaxf(r * Tf + offv - 0.5f, 0.0f), Tf - 1.0f);
        float x0 = floorf(x);
        float w  = x - x0;
        int   i0 = (int)x0;
        int   i1 = min(i0 + 1, Ti - 1);
        int   g0 = (n * S_TOT + st + i0) * DM + m * DH;
        int   g1 = (n * S_TOT + st + i1) * DM + m * DH;

        float mx = logit;
        #pragma unroll
        for (int o = 8; o > 0; o >>= 1)
            mx = fmaxf(mx, __shfl_xor_sync(0xffffffffu, mx, o, 16));
        float e = expf(logit - mx);
        float ssum = e;
        #pragma unroll
        for (int o = 8; o > 0; o >>= 1)
            ssum += __shfl_xor_sync(0xffffffffu, ssum, o, 16);
        float aw = e / ssum;

        if (lane < 16)
            sp[m][lp] = make_float4(__int_as_float(g0), __int_as_float(g1), w, aw);
    }
    __syncwarp();

    const int g = lane >> 3;
    const int c = lane & 7;
    float4 acc = make_float4(0.f, 0.f, 0.f, 0.f);
    #pragma unroll
    for (int t = 0; t < 4; t++) {
        float4 pr = sp[m][t * 4 + g];
        int   ig0 = __float_as_int(pr.x);
        int   ig1 = __float_as_int(pr.y);
        float w   = pr.z;
        float aw  = pr.w;
        float4 v0 = *(const float4*)(g_value + ig0 + c * 4);
        float4 v1 = *(const float4*)(g_value + ig1 + c * 4);
        acc.x = fmaf(aw, fmaf(w, v1.x - v0.x, v0.x), acc.x);
        acc.y = fmaf(aw, fmaf(w, v1.y - v0.y, v0.y), acc.y);
        acc.z = fmaf(aw, fmaf(w, v1.z - v0.z, v0.z), acc.z);
        acc.w = fmaf(aw, fmaf(w, v1.w - v0.w, v0.w), acc.w);
    }
    #pragma unroll
    for (int o = 8; o <= 16; o <<= 1) {
        acc.x += __shfl_xor_sync(0xffffffffu, acc.x, o);
        acc.y += __shfl_xor_sync(0xffffffffu, acc.y, o);
        acc.z += __shfl_xor_sync(0xffffffffu, acc.z, o);
        acc.w += __shfl_xor_sync(0xffffffffu, acc.w, o);
    }
    if (lane < 8) {
        acc.x = __uint_as_float(f2tf32(acc.x));
        acc.y = __uint_as_float(f2tf32(acc.y));
        acc.z = __uint_as_float(f2tf32(acc.z));
        acc.w = __uint_as_float(f2tf32(acc.w));
        *(float4*)(g_mid + (long)nq * DM + m * DH + c * 4) = acc;
    }
}

// ---------------- launch ------------------------------------------------------
extern "C" void kernel_launch(void* const* d_in, const int* in_sizes, int n_in,
                              void* d_out, int out_size)
{
    const float* query  = (const float*)d_in[0];
    const float* refpts = (const float*)d_in[1];
    const float* flat   = (const float*)d_in[2];
    const int*   shapes = (const int*)  d_in[3];
    const int*   start  = (const int*)  d_in[4];
    const float* W_off  = (const float*)d_in[5];
    const float* b_off  = (const float*)d_in[6];
    const float* W_aw   = (const float*)d_in[7];
    const float* b_aw   = (const float*)d_in[8];
    const float* W_v    = (const float*)d_in[9];
    const float* b_v    = (const float*)d_in[10];
    const float* W_out  = (const float*)d_in[11];
    const float* b_out  = (const float*)d_in[12];
    float* out = (float*)d_out;

    float *p_value, *p_oa, *p_mid, *p_BtV, *p_BtOA, *p_BtO, *p_bOA;
    cudaGetSymbolAddress((void**)&p_value, g_value);
    cudaGetSymbolAddress((void**)&p_oa,    g_oa);
    cudaGetSymbolAddress((void**)&p_mid,   g_mid);
    cudaGetSymbolAddress((void**)&p_BtV,   g_BtV);
    cudaGetSymbolAddress((void**)&p_BtOA,  g_BtOA);
    cudaGetSymbolAddress((void**)&p_BtO,   g_BtO);
    cudaGetSymbolAddress((void**)&p_bOA,   g_bOA);

    const int smem_bytes = 4 * BUFW * 4;   // 73728
    cudaFuncSetAttribute(mma_gemm_kernel<true>,
                         cudaFuncAttributeMaxDynamicSharedMemorySize, smem_bytes);
    cudaFuncSetAttribute(mma_gemm_kernel<false>,
                         cudaFuncAttributeMaxDynamicSharedMemorySize, smem_bytes);

    // prep: weight transposes (tf32-rounded) + bias concat
    prep_kernel<<<193, dim3(32, 32)>>>(W_v, W_off, W_aw, W_out, b_off, b_aw);

    // fused GEMM1: value = flat@BtV + b_v  |  [off|aw] = query@BtOA + bOA
    mma_gemm_kernel<true><<<dim3(2, MV / 128 + MQ / 128), 256, smem_bytes>>>(
        flat, p_BtV, b_v, p_value, MV / 128,
        query, p_BtOA, p_bOA, p_oa);

    // sampling (writes tf32-rounded g_mid)
    msda_sample_kernel<<<MQ, 256>>>(refpts, shapes, start);

    // GEMM2: out = mid @ BtO + b_out (A already tf32 -> raw fragments)
    mma_gemm_kernel<false><<<dim3(2, MQ / 128), 256, smem_bytes>>>(
        p_mid, p_BtO, b_out, out, MQ / 128,
        p_mid, p_BtO, b_out, out);
}